// round 1
// baseline (speedup 1.0000x reference)
#include <cuda_runtime.h>
#include <math.h>

// ---------------- problem constants ----------------
#define BATCH   32
#define SEQ     197          // 196 patches + cls
#define NPATCH  196
#define DIM     768
#define NHEAD   12
#define HDIM    64
#define FFN     3072
#define NLAYER  12
#define NCLS    1000
#define QKVN    2304         // 3*768
#define MROWS   (BATCH*SEQ)  // 6304

// ---------------- scratch (device globals; no allocations) ----------------
__device__ float g_x   [(size_t)BATCH*SEQ*DIM];       // residual stream
__device__ float g_xn  [(size_t)BATCH*SEQ*DIM];       // LN output
__device__ float g_pat [(size_t)BATCH*NPATCH*DIM];    // extracted patches
__device__ float g_qkv [(size_t)MROWS*QKVN];          // fused qkv  [B,S, q|k|v]
__device__ float g_o   [(size_t)BATCH*SEQ*DIM];       // attention out (concat heads)
__device__ float g_h   [(size_t)MROWS*FFN];           // FFN hidden
__device__ float g_Wqkv[(size_t)NLAYER*DIM*QKVN];     // repacked [L, D, 3*768]
__device__ float g_bqkv[(size_t)NLAYER*QKVN];
__device__ float g_ln0 [(size_t)BATCH*DIM];           // head LN out

// ---------------- patch extraction ----------------
// patches[b,p,j] with p=py*14+px, j=(r*16+c)*3+ch  <-  images[b,py*16+r,px*16+c,ch]
__global__ void extract_patches_k(const float* __restrict__ img)
{
    size_t i = (size_t)blockIdx.x * blockDim.x + threadIdx.x;
    size_t total = (size_t)BATCH * NPATCH * DIM;
    if (i >= total) return;
    int b  = (int)(i / ((size_t)NPATCH * DIM));
    int r1 = (int)(i % ((size_t)NPATCH * DIM));
    int p  = r1 / DIM;
    int j  = r1 % DIM;
    int py = p / 14, px = p % 14;
    int r  = j / 48;
    int rem = j % 48;
    int c  = rem / 3, ch = rem % 3;
    size_t src = (((size_t)b*224 + py*16 + r)*224 + px*16 + c)*3 + ch;
    g_pat[i] = img[src];
}

// ---------------- cls fill ----------------
__global__ void cls_fill_k(const float* __restrict__ cls)
{
    int i = blockIdx.x * blockDim.x + threadIdx.x;
    if (i >= BATCH * DIM) return;
    int b = i / DIM, j = i % DIM;
    g_x[(size_t)b*SEQ*DIM + j] = cls[j];
}

// ---------------- QKV weight / bias repack ----------------
// src Wt[l,h,d,e] -> dst[l, d, t*768 + h*64 + e]
__global__ void pack_qkv_w_k(const float* __restrict__ Wq,
                             const float* __restrict__ Wk,
                             const float* __restrict__ Wv)
{
    size_t i = (size_t)blockIdx.x * blockDim.x + threadIdx.x;
    size_t per = (size_t)NLAYER * NHEAD * DIM * HDIM;   // 7,077,888
    if (i >= 3 * per) return;
    int t = (int)(i / per);
    size_t r = i % per;
    int l = (int)(r / ((size_t)NHEAD * DIM * HDIM));
    size_t r2 = r % ((size_t)NHEAD * DIM * HDIM);
    int h = (int)(r2 / (DIM * HDIM));
    int r3 = (int)(r2 % (DIM * HDIM));
    int d = r3 / HDIM, e = r3 % HDIM;
    const float* W = (t == 0) ? Wq : (t == 1) ? Wk : Wv;
    float v = W[(((size_t)l*NHEAD + h)*DIM + d)*HDIM + e];
    g_Wqkv[((size_t)l*DIM + d)*QKVN + t*DIM + h*HDIM + e] = v;
}

__global__ void pack_qkv_b_k(const float* __restrict__ bq,
                             const float* __restrict__ bk,
                             const float* __restrict__ bv)
{
    int i = blockIdx.x * blockDim.x + threadIdx.x;
    int per = NLAYER * DIM;   // 9216 (H*HD = 768 contiguous)
    if (i >= 3 * per) return;
    int t = i / per;
    int r = i % per;
    int l = r / DIM, c = r % DIM;
    const float* B = (t == 0) ? bq : (t == 1) ? bk : bv;
    g_bqkv[(size_t)l*QKVN + t*DIM + c] = B[l*DIM + c];
}

// ---------------- generic tiled SGEMM with epilogues ----------------
// C[M,N] = A[M,K] @ B[K,N] + bias[n]   (+ epilogue per mode)
// mode 0: bias
// mode 1: bias + resid[m,n]
// mode 2: gelu(bias+acc)  (exact erf)
// mode 3: patch embed: + pos[(m%196)*768+n], out row remapped to b*197+p+1
#define BM 64
#define BN 64
#define BK 16

__global__ void gemm_k(const float* __restrict__ A, const float* __restrict__ B,
                       const float* __restrict__ bias,
                       const float* __restrict__ extra,   // pos_emb (mode 3)
                       const float* __restrict__ resid,   // residual (mode 1)
                       float* __restrict__ C,
                       int M, int N, int K, int mode)
{
    __shared__ float As[BK][BM];
    __shared__ float Bs[BK][BN];

    int tid = threadIdx.x;            // 256
    int tx = tid & 15, ty = tid >> 4; // 16x16
    int n0 = blockIdx.x * BN, m0 = blockIdx.y * BM;

    int arow = tid >> 2;              // 0..63
    int acol = (tid & 3) * 4;         // 0,4,8,12
    int brow = tid >> 4;              // 0..15
    int bcol = (tid & 15) * 4;        // 0..60

    float acc[4][4] = {};

    for (int k0 = 0; k0 < K; k0 += BK) {
        // load A tile (row-major, float4)
        int am = m0 + arow;
        float4 av = make_float4(0.f, 0.f, 0.f, 0.f);
        if (am < M) av = *(const float4*)(A + (size_t)am * K + k0 + acol);
        As[acol + 0][arow] = av.x;
        As[acol + 1][arow] = av.y;
        As[acol + 2][arow] = av.z;
        As[acol + 3][arow] = av.w;
        // load B tile
        float4 bv = make_float4(0.f, 0.f, 0.f, 0.f);
        if (n0 + bcol < N) bv = *(const float4*)(B + (size_t)(k0 + brow) * N + n0 + bcol);
        Bs[brow][bcol + 0] = bv.x;
        Bs[brow][bcol + 1] = bv.y;
        Bs[brow][bcol + 2] = bv.z;
        Bs[brow][bcol + 3] = bv.w;
        __syncthreads();

        #pragma unroll
        for (int kk = 0; kk < BK; kk++) {
            float a[4], b[4];
            #pragma unroll
            for (int i = 0; i < 4; i++) a[i] = As[kk][ty * 4 + i];
            #pragma unroll
            for (int j = 0; j < 4; j++) b[j] = Bs[kk][tx * 4 + j];
            #pragma unroll
            for (int i = 0; i < 4; i++)
                #pragma unroll
                for (int j = 0; j < 4; j++)
                    acc[i][j] += a[i] * b[j];
        }
        __syncthreads();
    }

    #pragma unroll
    for (int i = 0; i < 4; i++) {
        int m = m0 + ty * 4 + i;
        if (m >= M) continue;
        #pragma unroll
        for (int j = 0; j < 4; j++) {
            int n = n0 + tx * 4 + j;
            if (n >= N) continue;
            float v = acc[i][j] + bias[n];
            if (mode == 1) {
                v += resid[(size_t)m * N + n];
                C[(size_t)m * N + n] = v;
            } else if (mode == 2) {
                v = 0.5f * v * (1.0f + erff(v * 0.70710678118654752f));
                C[(size_t)m * N + n] = v;
            } else if (mode == 3) {
                v += extra[(size_t)(m % NPATCH) * DIM + n];
                int orow = m + m / NPATCH + 1;   // b*197 + p + 1
                C[(size_t)orow * N + n] = v;
            } else {
                C[(size_t)m * N + n] = v;
            }
        }
    }
}

// ---------------- LayerNorm (1 block / row, 256 threads, D=768) ----------------
__global__ void layernorm_k(const float* __restrict__ x, long ld_in,
                            const float* __restrict__ g, const float* __restrict__ b,
                            float* __restrict__ out, long ld_out)
{
    int row = blockIdx.x;
    const float* xr = x + (size_t)row * ld_in;
    float* orow = out + (size_t)row * ld_out;
    int tid = threadIdx.x;
    float vals[3];
    float s = 0.f, s2 = 0.f;
    #pragma unroll
    for (int i = 0; i < 3; i++) {
        float v = xr[tid + i * 256];
        vals[i] = v; s += v; s2 += v * v;
    }
    #pragma unroll
    for (int o = 16; o > 0; o >>= 1) {
        s  += __shfl_xor_sync(0xFFFFFFFFu, s,  o);
        s2 += __shfl_xor_sync(0xFFFFFFFFu, s2, o);
    }
    __shared__ float rs[8], rs2[8];
    if ((tid & 31) == 0) { rs[tid >> 5] = s; rs2[tid >> 5] = s2; }
    __syncthreads();
    float tot = 0.f, tot2 = 0.f;
    #pragma unroll
    for (int i = 0; i < 8; i++) { tot += rs[i]; tot2 += rs2[i]; }
    float mean = tot * (1.0f / DIM);
    float var  = tot2 * (1.0f / DIM) - mean * mean;
    float inv  = rsqrtf(var + 1e-5f);
    #pragma unroll
    for (int i = 0; i < 3; i++) {
        int c = tid + i * 256;
        orow[c] = (vals[i] - mean) * inv * g[c] + b[c];
    }
}

// ---------------- fused attention: one block per (b, h, query-row) ----------------
// qkv layout: [b, s, (q|k|v) 3*768]; writes o[b, s, h*64+e]
__global__ void attn_k(float* __restrict__ o)
{
    int s = blockIdx.x, h = blockIdx.y, b = blockIdx.z;
    int tid = threadIdx.x;   // 128

    __shared__ float sq[64];
    __shared__ float sp[SEQ];
    __shared__ float wmax[4], wsum[4];
    __shared__ float so[2][64];

    const float* base = g_qkv + (size_t)b * SEQ * QKVN;
    if (tid < 64) sq[tid] = base[(size_t)s * QKVN + h * HDIM + tid];
    __syncthreads();

    float lmax = -1e30f;
    for (int j = tid; j < SEQ; j += 128) {
        const float4* kr = (const float4*)(base + (size_t)j * QKVN + DIM + h * HDIM);
        float d = 0.f;
        #pragma unroll
        for (int e = 0; e < 16; e++) {
            float4 kv4 = kr[e];
            float4 qv4 = *(const float4*)&sq[e * 4];
            d += kv4.x * qv4.x + kv4.y * qv4.y + kv4.z * qv4.z + kv4.w * qv4.w;
        }
        d *= 0.125f;
        sp[j] = d;
        lmax = fmaxf(lmax, d);
    }
    #pragma unroll
    for (int off = 16; off > 0; off >>= 1)
        lmax = fmaxf(lmax, __shfl_xor_sync(0xFFFFFFFFu, lmax, off));
    if ((tid & 31) == 0) wmax[tid >> 5] = lmax;
    __syncthreads();
    float m = fmaxf(fmaxf(wmax[0], wmax[1]), fmaxf(wmax[2], wmax[3]));

    float lsum = 0.f;
    for (int j = tid; j < SEQ; j += 128) {
        float p = __expf(sp[j] - m);
        sp[j] = p;
        lsum += p;
    }
    #pragma unroll
    for (int off = 16; off > 0; off >>= 1)
        lsum += __shfl_xor_sync(0xFFFFFFFFu, lsum, off);
    if ((tid & 31) == 0) wsum[tid >> 5] = lsum;
    __syncthreads();
    float inv = 1.0f / (wsum[0] + wsum[1] + wsum[2] + wsum[3]);

    int e = tid & 63, half = tid >> 6;
    float acc = 0.f;
    for (int j = half; j < SEQ; j += 2)
        acc += sp[j] * base[(size_t)j * QKVN + 2 * DIM + h * HDIM + e];
    so[half][e] = acc;
    __syncthreads();
    if (tid < 64)
        o[(size_t)(b * SEQ + s) * DIM + h * HDIM + tid] = (so[0][tid] + so[1][tid]) * inv;
}

// ---------------- host orchestration ----------------
extern "C" void kernel_launch(void* const* d_in, const int* in_sizes, int n_in,
                              void* d_out, int out_size)
{
    const float* images    = (const float*)d_in[0];
    const float* patch_W   = (const float*)d_in[1];
    const float* patch_b   = (const float*)d_in[2];
    const float* pos_emb   = (const float*)d_in[3];
    const float* cls       = (const float*)d_in[4];
    const float* ln1_g     = (const float*)d_in[5];
    const float* ln1_b     = (const float*)d_in[6];
    const float* Wq        = (const float*)d_in[7];
    const float* bq        = (const float*)d_in[8];
    const float* Wk        = (const float*)d_in[9];
    const float* bk        = (const float*)d_in[10];
    const float* Wv        = (const float*)d_in[11];
    const float* bv        = (const float*)d_in[12];
    const float* Wo        = (const float*)d_in[13];
    const float* bo        = (const float*)d_in[14];
    const float* ln2_g     = (const float*)d_in[15];
    const float* ln2_b     = (const float*)d_in[16];
    const float* W1        = (const float*)d_in[17];
    const float* b1        = (const float*)d_in[18];
    const float* W2        = (const float*)d_in[19];
    const float* b2        = (const float*)d_in[20];
    const float* head_g    = (const float*)d_in[21];
    const float* head_bn   = (const float*)d_in[22];
    const float* head_W    = (const float*)d_in[23];
    const float* head_bias = (const float*)d_in[24];
    float* out = (float*)d_out;

    float *px, *pxn, *ppat, *pqkv, *po, *ph, *pWqkv, *pbqkv, *pln0;
    cudaGetSymbolAddress((void**)&px,    g_x);
    cudaGetSymbolAddress((void**)&pxn,   g_xn);
    cudaGetSymbolAddress((void**)&ppat,  g_pat);
    cudaGetSymbolAddress((void**)&pqkv,  g_qkv);
    cudaGetSymbolAddress((void**)&po,    g_o);
    cudaGetSymbolAddress((void**)&ph,    g_h);
    cudaGetSymbolAddress((void**)&pWqkv, g_Wqkv);
    cudaGetSymbolAddress((void**)&pbqkv, g_bqkv);
    cudaGetSymbolAddress((void**)&pln0,  g_ln0);

    // ---- prologue: patches, cls, weight repack ----
    {
        size_t tot = (size_t)BATCH * NPATCH * DIM;
        extract_patches_k<<<(unsigned)((tot + 255) / 256), 256>>>(images);
    }
    cls_fill_k<<<(BATCH * DIM + 255) / 256, 256>>>(cls);
    {
        size_t tot = (size_t)3 * NLAYER * NHEAD * DIM * HDIM;
        pack_qkv_w_k<<<(unsigned)((tot + 255) / 256), 256>>>(Wq, Wk, Wv);
    }
    pack_qkv_b_k<<<(3 * NLAYER * DIM + 255) / 256, 256>>>(bq, bk, bv);

    // ---- patch embed GEMM (mode 3): g_x[b, 1+p, :] = pat @ patch_W + b + pos ----
    {
        dim3 grid((DIM + BN - 1) / BN, (BATCH * NPATCH + BM - 1) / BM);
        gemm_k<<<grid, 256>>>(ppat, patch_W, patch_b, pos_emb, nullptr, px,
                              BATCH * NPATCH, DIM, DIM, 3);
    }

    // ---- transformer layers ----
    for (int l = 0; l < NLAYER; l++) {
        // LN1
        layernorm_k<<<MROWS, 256>>>(px, DIM, ln1_g + (size_t)l * DIM,
                                    ln1_b + (size_t)l * DIM, pxn, DIM);
        // QKV GEMM: [6304,768] @ [768,2304]
        {
            dim3 grid((QKVN + BN - 1) / BN, (MROWS + BM - 1) / BM);
            gemm_k<<<grid, 256>>>(pxn, pWqkv + (size_t)l * DIM * QKVN,
                                  pbqkv + (size_t)l * QKVN, nullptr, nullptr,
                                  pqkv, MROWS, QKVN, DIM, 0);
        }
        // attention
        {
            dim3 grid(SEQ, NHEAD, BATCH);
            attn_k<<<grid, 128>>>(po);
        }
        // proj + residual: x += o @ Wo + bo
        {
            dim3 grid((DIM + BN - 1) / BN, (MROWS + BM - 1) / BM);
            gemm_k<<<grid, 256>>>(po, Wo + (size_t)l * DIM * DIM,
                                  bo + (size_t)l * DIM, nullptr, px, px,
                                  MROWS, DIM, DIM, 1);
        }
        // LN2
        layernorm_k<<<MROWS, 256>>>(px, DIM, ln2_g + (size_t)l * DIM,
                                    ln2_b + (size_t)l * DIM, pxn, DIM);
        // FFN up + gelu: h = gelu(xn @ W1 + b1)
        {
            dim3 grid((FFN + BN - 1) / BN, (MROWS + BM - 1) / BM);
            gemm_k<<<grid, 256>>>(pxn, W1 + (size_t)l * DIM * FFN,
                                  b1 + (size_t)l * FFN, nullptr, nullptr,
                                  ph, MROWS, FFN, DIM, 2);
        }
        // FFN down + residual: x += h @ W2 + b2
        {
            dim3 grid((DIM + BN - 1) / BN, (MROWS + BM - 1) / BM);
            gemm_k<<<grid, 256>>>(ph, W2 + (size_t)l * FFN * DIM,
                                  b2 + (size_t)l * DIM, nullptr, px, px,
                                  MROWS, DIM, FFN, 1);
        }
    }

    // ---- head: LN on x[:,0,:] then GEMM [32,768]@[768,1000] ----
    layernorm_k<<<BATCH, 256>>>(px, (long)SEQ * DIM, head_g, head_bn, pln0, DIM);
    {
        dim3 grid((NCLS + BN - 1) / BN, (BATCH + BM - 1) / BM);
        gemm_k<<<grid, 256>>>(pln0, head_W, head_bias, nullptr, nullptr,
                              out, BATCH, NCLS, DIM, 0);
    }
}

// round 6
// speedup vs baseline: 2.0040x; 2.0040x over previous
#include <cuda_runtime.h>
#include <math.h>
#include <stdint.h>

// ---------------- problem constants ----------------
#define BATCH   32
#define SEQ     197
#define NPATCH  196
#define DIM     768
#define NHEAD   12
#define HDIM    64
#define FFN     3072
#define NLAYER  12
#define NCLS    1000
#define QKVN    2304
#define MROWS   (BATCH*SEQ)    // 6304
#define PATM    (BATCH*NPATCH) // 6272

// ---------------- scratch (device globals; no allocations) ----------------
__device__ float g_x   [(size_t)MROWS*DIM];
__device__ float g_xn  [(size_t)MROWS*DIM];
__device__ float g_pat [(size_t)PATM*DIM];
__device__ float g_qkv [(size_t)MROWS*QKVN];
__device__ float g_o   [(size_t)MROWS*DIM];
__device__ float g_h   [(size_t)MROWS*FFN];
__device__ float g_Wqkv[(size_t)NLAYER*DIM*QKVN];    // [L][K=768][N=2304] staging
__device__ float g_bqkv[(size_t)NLAYER*QKVN];
__device__ float g_ln0 [(size_t)BATCH*DIM];
// transposed (N-major, K contiguous) tf32-rounded weights
__device__ float g_WqkvT[(size_t)NLAYER*QKVN*DIM];
__device__ float g_WoT  [(size_t)NLAYER*DIM*DIM];
__device__ float g_W1T  [(size_t)NLAYER*FFN*DIM];
__device__ float g_W2T  [(size_t)NLAYER*DIM*FFN];
__device__ float g_PWT  [(size_t)DIM*DIM];

// ---------------- helpers ----------------
__device__ __forceinline__ float tf32r(float x) {
    uint32_t u;
    asm("cvt.rna.tf32.f32 %0, %1;" : "=r"(u) : "f"(x));
    return __uint_as_float(u);
}

__device__ __forceinline__ uint32_t smem_u32(const void* p) {
    uint32_t a;
    asm("{ .reg .u64 t; cvta.to.shared.u64 t, %1; cvt.u32.u64 %0, t; }" : "=r"(a) : "l"(p));
    return a;
}

__device__ __forceinline__ void cpa16(uint32_t s, const void* g, bool p) {
    int n = p ? 16 : 0;
    asm volatile("cp.async.cg.shared.global [%0], [%1], 16, %2;"
                 :: "r"(s), "l"(g), "r"(n));
}
#define CP_COMMIT() asm volatile("cp.async.commit_group;" ::: "memory")
#define CP_WAIT1()  asm volatile("cp.async.wait_group 1;" ::: "memory")

__device__ __forceinline__ void mma_tf32(float* c, const uint32_t* a, const uint32_t* b) {
    asm volatile(
        "mma.sync.aligned.m16n8k8.row.col.f32.tf32.tf32.f32 "
        "{%0,%1,%2,%3}, {%4,%5,%6,%7}, {%8,%9}, {%0,%1,%2,%3};"
        : "+f"(c[0]), "+f"(c[1]), "+f"(c[2]), "+f"(c[3])
        : "r"(a[0]), "r"(a[1]), "r"(a[2]), "r"(a[3]), "r"(b[0]), "r"(b[1]));
}

// ---------------- patch extraction (tf32-rounded output) ----------------
__global__ void extract_patches_k(const float* __restrict__ img)
{
    size_t i = (size_t)blockIdx.x * blockDim.x + threadIdx.x;
    size_t total = (size_t)PATM * DIM;
    if (i >= total) return;
    int b  = (int)(i / ((size_t)NPATCH * DIM));
    int r1 = (int)(i % ((size_t)NPATCH * DIM));
    int p  = r1 / DIM;
    int j  = r1 % DIM;
    int py = p / 14, px = p % 14;
    int r  = j / 48;
    int rem = j % 48;
    int c  = rem / 3, ch = rem % 3;
    size_t src = (((size_t)b*224 + py*16 + r)*224 + px*16 + c)*3 + ch;
    g_pat[i] = tf32r(img[src]);
}

__global__ void cls_fill_k(const float* __restrict__ cls)
{
    int i = blockIdx.x * blockDim.x + threadIdx.x;
    if (i >= BATCH * DIM) return;
    int b = i / DIM, j = i % DIM;
    g_x[(size_t)b*SEQ*DIM + j] = cls[j];
}

// ---------------- QKV weight staging [L][K][N] ----------------
__global__ void pack_qkv_w_k(const float* __restrict__ Wq,
                             const float* __restrict__ Wk,
                             const float* __restrict__ Wv)
{
    size_t i = (size_t)blockIdx.x * blockDim.x + threadIdx.x;
    size_t per = (size_t)NLAYER * NHEAD * DIM * HDIM;
    if (i >= 3 * per) return;
    int t = (int)(i / per);
    size_t r = i % per;
    int l = (int)(r / ((size_t)NHEAD * DIM * HDIM));
    size_t r2 = r % ((size_t)NHEAD * DIM * HDIM);
    int h = (int)(r2 / (DIM * HDIM));
    int r3 = (int)(r2 % (DIM * HDIM));
    int d = r3 / HDIM, e = r3 % HDIM;
    const float* W = (t == 0) ? Wq : (t == 1) ? Wk : Wv;
    float v = W[(((size_t)l*NHEAD + h)*DIM + d)*HDIM + e];
    g_Wqkv[((size_t)l*DIM + d)*QKVN + t*DIM + h*HDIM + e] = v;
}

__global__ void pack_qkv_b_k(const float* __restrict__ bq,
                             const float* __restrict__ bk,
                             const float* __restrict__ bv)
{
    int i = blockIdx.x * blockDim.x + threadIdx.x;
    int per = NLAYER * DIM;
    if (i >= 3 * per) return;
    int t = i / per;
    int r = i % per;
    int l = r / DIM, c = r % DIM;
    const float* B = (t == 0) ? bq : (t == 1) ? bk : bv;
    g_bqkv[(size_t)l*QKVN + t*DIM + c] = B[l*DIM + c];
}

// ---------------- tiled transpose + tf32 round: [l][K][N] -> [l][N][K] ----------------
__global__ void transpose_pack_k(const float* __restrict__ src, float* __restrict__ dst,
                                 int K, int N)
{
    __shared__ float t[32][33];
    int l = blockIdx.z;
    const float* s = src + (size_t)l * K * N;
    float* d = dst + (size_t)l * K * N;
    int n0 = blockIdx.x * 32, k0 = blockIdx.y * 32;
    int tx = threadIdx.x, ty = threadIdx.y;  // 32x8
    #pragma unroll
    for (int j = 0; j < 32; j += 8)
        t[ty + j][tx] = s[(size_t)(k0 + ty + j) * N + n0 + tx];
    __syncthreads();
    #pragma unroll
    for (int j = 0; j < 32; j += 8)
        d[(size_t)(n0 + ty + j) * K + k0 + tx] = tf32r(t[tx][ty + j]);
}

// ---------------- tf32 mma.sync GEMM, 128x128 tile, BK=32, 256 threads ----------------
// C[M,N] = A[M,K] @ Wt[N,K]^T + bias[n]
// mode 0: bias; 1: bias+resid; 2: gelu (tf32-rounded out); 3: +pos emb, row remap
#define ASTRIDE 36
#define BUF_FLOATS (2 * 128 * ASTRIDE)            // A + B per stage
#define GM_SMEM_BYTES (2 * BUF_FLOATS * 4)        // 2 stages = 73728 B

__global__ __launch_bounds__(256, 1) void gemm_mma(
    const float* __restrict__ A, const float* __restrict__ Wt,
    const float* __restrict__ bias, const float* __restrict__ extra,
    const float* __restrict__ resid, float* __restrict__ C,
    int M, int N, int K, int mode)
{
    extern __shared__ __align__(16) float smem[];
    uint32_t sbase = smem_u32(smem);

    int tid = threadIdx.x;
    int wid = tid >> 5, lane = tid & 31;
    int wm = wid >> 2, wn = wid & 3;          // warp grid 2 x 4
    int g = lane >> 2, t4 = lane & 3;
    int m0 = blockIdx.y * 128, n0 = blockIdx.x * 128;
    int KI = K >> 5;

    const float* gA0 = A + (size_t)m0 * K;
    const float* gB0 = Wt + (size_t)n0 * K;

    float acc[64];
    #pragma unroll
    for (int i = 0; i < 64; i++) acc[i] = 0.f;

    auto load_tile = [&](int i, int buf) {
        size_t ko = (size_t)i * 32;
        uint32_t sA = sbase + (uint32_t)buf * BUF_FLOATS * 4;
        uint32_t sB = sA + 128 * ASTRIDE * 4;
        #pragma unroll
        for (int j = 0; j < 4; j++) {
            int cidx = tid + j * 256;
            int r = cidx >> 3, c = cidx & 7;
            bool pa = (m0 + r) < M;
            cpa16(sA + (uint32_t)(r * ASTRIDE + c * 4) * 4,
                  gA0 + (size_t)(pa ? r : 0) * K + ko + c * 4, pa);
            cpa16(sB + (uint32_t)(r * ASTRIDE + c * 4) * 4,
                  gB0 + (size_t)r * K + ko + c * 4, true);
        }
    };

    load_tile(0, 0);
    CP_COMMIT();

    for (int i = 0; i < KI; i++) {
        if (i + 1 < KI) load_tile(i + 1, (i + 1) & 1);
        CP_COMMIT();
        CP_WAIT1();
        __syncthreads();

        const float* sA = smem + (i & 1) * BUF_FLOATS;
        const float* sB = sA + 128 * ASTRIDE;

        #pragma unroll
        for (int kk = 0; kk < 32; kk += 8) {
            uint32_t af[16], bf[8];
            #pragma unroll
            for (int mt = 0; mt < 4; mt++) {
                int rb = wm * 64 + mt * 16;
                af[mt*4+0] = __float_as_uint(sA[(rb + g)     * ASTRIDE + kk + t4]);
                af[mt*4+1] = __float_as_uint(sA[(rb + g + 8) * ASTRIDE + kk + t4]);
                af[mt*4+2] = __float_as_uint(sA[(rb + g)     * ASTRIDE + kk + t4 + 4]);
                af[mt*4+3] = __float_as_uint(sA[(rb + g + 8) * ASTRIDE + kk + t4 + 4]);
            }
            #pragma unroll
            for (int nt = 0; nt < 4; nt++) {
                int nb = wn * 32 + nt * 8;
                bf[nt*2+0] = __float_as_uint(sB[(nb + g) * ASTRIDE + kk + t4]);
                bf[nt*2+1] = __float_as_uint(sB[(nb + g) * ASTRIDE + kk + t4 + 4]);
            }
            #pragma unroll
            for (int mt = 0; mt < 4; mt++)
                #pragma unroll
                for (int nt = 0; nt < 4; nt++)
                    mma_tf32(&acc[(mt * 4 + nt) * 4], &af[mt * 4], &bf[nt * 2]);
        }
        __syncthreads();
    }

    // ---- epilogue ----
    #pragma unroll
    for (int mt = 0; mt < 4; mt++) {
        #pragma unroll
        for (int nt = 0; nt < 4; nt++) {
            float* c4 = &acc[(mt * 4 + nt) * 4];
            int col = n0 + wn * 32 + nt * 8 + 2 * t4;
            #pragma unroll
            for (int half = 0; half < 2; half++) {
                int m = m0 + wm * 64 + mt * 16 + g + half * 8;
                if (m >= M) continue;
                float v0 = c4[half * 2 + 0] + bias[col];
                float v1 = c4[half * 2 + 1] + bias[col + 1];
                int orow = m;
                if (mode == 1) {
                    const float* rr = resid + (size_t)m * N + col;
                    v0 += rr[0]; v1 += rr[1];
                } else if (mode == 2) {
                    v0 = tf32r(0.5f * v0 * (1.0f + erff(v0 * 0.70710678118654752f)));
                    v1 = tf32r(0.5f * v1 * (1.0f + erff(v1 * 0.70710678118654752f)));
                } else if (mode == 3) {
                    const float* pp = extra + (size_t)(m % NPATCH) * DIM + col;
                    v0 += pp[0]; v1 += pp[1];
                    orow = m + m / NPATCH + 1;
                }
                float2 v = make_float2(v0, v1);
                *(float2*)(C + (size_t)orow * N + col) = v;
            }
        }
    }
}

// ---------------- fp32 fallback GEMM (head only) ----------------
#define BM 64
#define BN 64
#define BK 16
__global__ void gemm_k(const float* __restrict__ A, const float* __restrict__ B,
                       const float* __restrict__ bias, float* __restrict__ C,
                       int M, int N, int K)
{
    __shared__ float As[BK][BM];
    __shared__ float Bs[BK][BN];
    int tid = threadIdx.x;
    int tx = tid & 15, ty = tid >> 4;
    int n0 = blockIdx.x * BN, m0 = blockIdx.y * BM;
    int arow = tid >> 2, acol = (tid & 3) * 4;
    int brow = tid >> 4, bcol = (tid & 15) * 4;
    float acc[4][4] = {};
    for (int k0 = 0; k0 < K; k0 += BK) {
        int am = m0 + arow;
        float4 av = make_float4(0.f, 0.f, 0.f, 0.f);
        if (am < M) av = *(const float4*)(A + (size_t)am * K + k0 + acol);
        As[acol+0][arow] = av.x; As[acol+1][arow] = av.y;
        As[acol+2][arow] = av.z; As[acol+3][arow] = av.w;
        float4 bv = make_float4(0.f, 0.f, 0.f, 0.f);
        if (n0 + bcol < N) bv = *(const float4*)(B + (size_t)(k0 + brow) * N + n0 + bcol);
        Bs[brow][bcol+0] = bv.x; Bs[brow][bcol+1] = bv.y;
        Bs[brow][bcol+2] = bv.z; Bs[brow][bcol+3] = bv.w;
        __syncthreads();
        #pragma unroll
        for (int kk = 0; kk < BK; kk++) {
            float a[4], b[4];
            #pragma unroll
            for (int i = 0; i < 4; i++) a[i] = As[kk][ty*4+i];
            #pragma unroll
            for (int j = 0; j < 4; j++) b[j] = Bs[kk][tx*4+j];
            #pragma unroll
            for (int i = 0; i < 4; i++)
                #pragma unroll
                for (int j = 0; j < 4; j++)
                    acc[i][j] += a[i] * b[j];
        }
        __syncthreads();
    }
    #pragma unroll
    for (int i = 0; i < 4; i++) {
        int m = m0 + ty*4 + i;
        if (m >= M) continue;
        #pragma unroll
        for (int j = 0; j < 4; j++) {
            int n = n0 + tx*4 + j;
            if (n >= N) continue;
            C[(size_t)m * N + n] = acc[i][j] + bias[n];
        }
    }
}

// ---------------- LayerNorm ----------------
__global__ void layernorm_k(const float* __restrict__ x, long ld_in,
                            const float* __restrict__ g, const float* __restrict__ b,
                            float* __restrict__ out, long ld_out, int rnd)
{
    int row = blockIdx.x;
    const float* xr = x + (size_t)row * ld_in;
    float* orow = out + (size_t)row * ld_out;
    int tid = threadIdx.x;
    float vals[3];
    float s = 0.f, s2 = 0.f;
    #pragma unroll
    for (int i = 0; i < 3; i++) {
        float v = xr[tid + i * 256];
        vals[i] = v; s += v; s2 += v * v;
    }
    #pragma unroll
    for (int o = 16; o > 0; o >>= 1) {
        s  += __shfl_xor_sync(0xFFFFFFFFu, s,  o);
        s2 += __shfl_xor_sync(0xFFFFFFFFu, s2, o);
    }
    __shared__ float rs[8], rs2[8];
    if ((tid & 31) == 0) { rs[tid >> 5] = s; rs2[tid >> 5] = s2; }
    __syncthreads();
    float tot = 0.f, tot2 = 0.f;
    #pragma unroll
    for (int i = 0; i < 8; i++) { tot += rs[i]; tot2 += rs2[i]; }
    float mean = tot * (1.0f / DIM);
    float var  = tot2 * (1.0f / DIM) - mean * mean;
    float inv  = rsqrtf(var + 1e-5f);
    #pragma unroll
    for (int i = 0; i < 3; i++) {
        int c = tid + i * 256;
        float v = (vals[i] - mean) * inv * g[c] + b[c];
        orow[c] = rnd ? tf32r(v) : v;
    }
}

// ---------------- fused attention (fp32, one block per (b,h,query)) ----------------
__global__ void attn_k(float* __restrict__ o)
{
    int s = blockIdx.x, h = blockIdx.y, b = blockIdx.z;
    int tid = threadIdx.x;   // 128
    __shared__ float sq[64];
    __shared__ float sp[SEQ];
    __shared__ float wmax[4], wsum[4];
    __shared__ float so[2][64];

    const float* base = g_qkv + (size_t)b * SEQ * QKVN;
    if (tid < 64) sq[tid] = base[(size_t)s * QKVN + h * HDIM + tid];
    __syncthreads();

    float lmax = -1e30f;
    for (int j = tid; j < SEQ; j += 128) {
        const float4* kr = (const float4*)(base + (size_t)j * QKVN + DIM + h * HDIM);
        float d = 0.f;
        #pragma unroll
        for (int e = 0; e < 16; e++) {
            float4 kv4 = kr[e];
            float4 qv4 = *(const float4*)&sq[e * 4];
            d += kv4.x * qv4.x + kv4.y * qv4.y + kv4.z * qv4.z + kv4.w * qv4.w;
        }
        d *= 0.125f;
        sp[j] = d;
        lmax = fmaxf(lmax, d);
    }
    #pragma unroll
    for (int off = 16; off > 0; off >>= 1)
        lmax = fmaxf(lmax, __shfl_xor_sync(0xFFFFFFFFu, lmax, off));
    if ((tid & 31) == 0) wmax[tid >> 5] = lmax;
    __syncthreads();
    float m = fmaxf(fmaxf(wmax[0], wmax[1]), fmaxf(wmax[2], wmax[3]));

    float lsum = 0.f;
    for (int j = tid; j < SEQ; j += 128) {
        float p = __expf(sp[j] - m);
        sp[j] = p;
        lsum += p;
    }
    #pragma unroll
    for (int off = 16; off > 0; off >>= 1)
        lsum += __shfl_xor_sync(0xFFFFFFFFu, lsum, off);
    if ((tid & 31) == 0) wsum[tid >> 5] = lsum;
    __syncthreads();
    float inv = 1.0f / (wsum[0] + wsum[1] + wsum[2] + wsum[3]);

    int e = tid & 63, half = tid >> 6;
    float acc = 0.f;
    for (int j = half; j < SEQ; j += 2)
        acc += sp[j] * base[(size_t)j * QKVN + 2 * DIM + h * HDIM + e];
    so[half][e] = acc;
    __syncthreads();
    if (tid < 64)
        o[(size_t)(b * SEQ + s) * DIM + h * HDIM + tid] = tf32r((so[0][tid] + so[1][tid]) * inv);
}

// ---------------- host orchestration ----------------
extern "C" void kernel_launch(void* const* d_in, const int* in_sizes, int n_in,
                              void* d_out, int out_size)
{
    const float* images    = (const float*)d_in[0];
    const float* patch_W   = (const float*)d_in[1];
    const float* patch_b   = (const float*)d_in[2];
    const float* pos_emb   = (const float*)d_in[3];
    const float* cls       = (const float*)d_in[4];
    const float* ln1_g     = (const float*)d_in[5];
    const float* ln1_b     = (const float*)d_in[6];
    const float* Wq        = (const float*)d_in[7];
    const float* bq        = (const float*)d_in[8];
    const float* Wk        = (const float*)d_in[9];
    const float* bk        = (const float*)d_in[10];
    const float* Wv        = (const float*)d_in[11];
    const float* bv        = (const float*)d_in[12];
    const float* Wo        = (const float*)d_in[13];
    const float* bo        = (const float*)d_in[14];
    const float* ln2_g     = (const float*)d_in[15];
    const float* ln2_b     = (const float*)d_in[16];
    const float* W1        = (const float*)d_in[17];
    const float* b1        = (const float*)d_in[18];
    const float* W2        = (const float*)d_in[19];
    const float* b2        = (const float*)d_in[20];
    const float* head_g    = (const float*)d_in[21];
    const float* head_bn   = (const float*)d_in[22];
    const float* head_W    = (const float*)d_in[23];
    const float* head_bias = (const float*)d_in[24];
    float* out = (float*)d_out;

    static int smem_set = 0;
    if (!smem_set) {
        cudaFuncSetAttribute(gemm_mma, cudaFuncAttributeMaxDynamicSharedMemorySize, GM_SMEM_BYTES);
        smem_set = 1;
    }

    float *px, *pxn, *ppat, *pqkv, *po, *ph, *pWqkv, *pbqkv, *pln0;
    float *pWqkvT, *pWoT, *pW1T, *pW2T, *pPWT;
    cudaGetSymbolAddress((void**)&px,     g_x);
    cudaGetSymbolAddress((void**)&pxn,    g_xn);
    cudaGetSymbolAddress((void**)&ppat,   g_pat);
    cudaGetSymbolAddress((void**)&pqkv,   g_qkv);
    cudaGetSymbolAddress((void**)&po,     g_o);
    cudaGetSymbolAddress((void**)&ph,     g_h);
    cudaGetSymbolAddress((void**)&pWqkv,  g_Wqkv);
    cudaGetSymbolAddress((void**)&pbqkv,  g_bqkv);
    cudaGetSymbolAddress((void**)&pln0,   g_ln0);
    cudaGetSymbolAddress((void**)&pWqkvT, g_WqkvT);
    cudaGetSymbolAddress((void**)&pWoT,   g_WoT);
    cudaGetSymbolAddress((void**)&pW1T,   g_W1T);
    cudaGetSymbolAddress((void**)&pW2T,   g_W2T);
    cudaGetSymbolAddress((void**)&pPWT,   g_PWT);

    // ---- prologue: patches, cls, weight packing/transposition ----
    {
        size_t tot = (size_t)PATM * DIM;
        extract_patches_k<<<(unsigned)((tot + 255) / 256), 256>>>(images);
    }
    cls_fill_k<<<(BATCH * DIM + 255) / 256, 256>>>(cls);
    {
        size_t tot = (size_t)3 * NLAYER * NHEAD * DIM * HDIM;
        pack_qkv_w_k<<<(unsigned)((tot + 255) / 256), 256>>>(Wq, Wk, Wv);
    }
    pack_qkv_b_k<<<(3 * NLAYER * DIM + 255) / 256, 256>>>(bq, bk, bv);

    dim3 tb(32, 8);
    transpose_pack_k<<<dim3(QKVN/32, DIM/32, NLAYER), tb>>>(pWqkv, pWqkvT, DIM, QKVN);
    transpose_pack_k<<<dim3(DIM/32,  DIM/32, NLAYER), tb>>>(Wo,    pWoT,   DIM, DIM);
    transpose_pack_k<<<dim3(FFN/32,  DIM/32, NLAYER), tb>>>(W1,    pW1T,   DIM, FFN);
    transpose_pack_k<<<dim3(DIM/32,  FFN/32, NLAYER), tb>>>(W2,    pW2T,   FFN, DIM);
    transpose_pack_k<<<dim3(DIM/32,  DIM/32, 1),      tb>>>(patch_W, pPWT, DIM, DIM);

    // ---- patch embed: g_x[b,1+p,:] = pat @ patch_W + b + pos ----
    gemm_mma<<<dim3(DIM/128, PATM/128), 256, GM_SMEM_BYTES>>>(
        ppat, pPWT, patch_b, pos_emb, nullptr, px, PATM, DIM, DIM, 3);

    int mt = (MROWS + 127) / 128;  // 50

    for (int l = 0; l < NLAYER; l++) {
        layernorm_k<<<MROWS, 256>>>(px, DIM, ln1_g + (size_t)l*DIM, ln1_b + (size_t)l*DIM,
                                    pxn, DIM, 1);
        gemm_mma<<<dim3(QKVN/128, mt), 256, GM_SMEM_BYTES>>>(
            pxn, pWqkvT + (size_t)l*QKVN*DIM, pbqkv + (size_t)l*QKVN,
            nullptr, nullptr, pqkv, MROWS, QKVN, DIM, 0);
        {
            dim3 grid(SEQ, NHEAD, BATCH);
            attn_k<<<grid, 128>>>(po);
        }
        gemm_mma<<<dim3(DIM/128, mt), 256, GM_SMEM_BYTES>>>(
            po, pWoT + (size_t)l*DIM*DIM, bo + (size_t)l*DIM,
            nullptr, px, px, MROWS, DIM, DIM, 1);
        layernorm_k<<<MROWS, 256>>>(px, DIM, ln2_g + (size_t)l*DIM, ln2_b + (size_t)l*DIM,
                                    pxn, DIM, 1);
        gemm_mma<<<dim3(FFN/128, mt), 256, GM_SMEM_BYTES>>>(
            pxn, pW1T + (size_t)l*FFN*DIM, b1 + (size_t)l*FFN,
            nullptr, nullptr, ph, MROWS, FFN, DIM, 2);
        gemm_mma<<<dim3(DIM/128, mt), 256, GM_SMEM_BYTES>>>(
            ph, pW2T + (size_t)l*DIM*FFN, b2 + (size_t)l*DIM,
            nullptr, px, px, MROWS, DIM, FFN, 1);
    }

    // ---- head ----
    layernorm_k<<<BATCH, 256>>>(px, (long)SEQ * DIM, head_g, head_bn, pln0, DIM, 0);
    {
        dim3 grid((NCLS + BN - 1) / BN, (BATCH + BM - 1) / BM);
        gemm_k<<<grid, 256>>>(pln0, head_W, head_bias, out, BATCH, NCLS, DIM);
    }
}